// round 11
// baseline (speedup 1.0000x reference)
#include <cuda_runtime.h>
#include <cstdint>

// ---------------------------------------------------------------------------
// MGPATH Sinkhorn-OT head. R11: two-kernel split.
//  A: max-occupancy streaming GEMM (2048 blk x 256 thr, 32 warps/SM, 64 regs)
//     -> g_sim [65536 x 8] (2 MB device scratch).
//  B: persistent 148-block Sinkhorn tail (R6-verified machinery), reads g_sim.
// ---------------------------------------------------------------------------

#define M_ROWS 65536
#define D_DIM  1024
#define NBLK   148
#define NTHR   448
#define NWARP  14
#define NGROUPS 2048
#define ANTHR  256
#define SINK_MAX_ITER 100
#define SINK_THRESH 0.01f

__device__ float             g_sim[M_ROWS * 8];   // 2 MB scratch
__device__ volatile float    g_part[2][NBLK * 16];
__device__ unsigned          g_cnt;
__device__ volatile unsigned g_gen;

__global__ void mg_init() { g_cnt = 0u; g_gen = 0u; }

// sense-reversing grid barrier; all NBLK blocks co-resident (1/SM, 148 SMs)
__device__ __forceinline__ void grid_barrier(unsigned &mygen) {
    __syncthreads();
    if (threadIdx.x == 0) {
        __threadfence();
        unsigned prev = atomicAdd(&g_cnt, 1u);
        if (prev == NBLK - 1) {
            g_cnt = 0u;
            __threadfence();
            g_gen = mygen + 1u;
        } else {
            while (g_gen == mygen) { __nanosleep(32); }
        }
        __threadfence();
    }
    __syncthreads();
    mygen++;
}

template <int NV>
__device__ __forceinline__ void block_reduce(float* vals, float* red) {
    #pragma unroll
    for (int i = 0; i < NV; i++) {
        #pragma unroll
        for (int o = 16; o > 0; o >>= 1)
            vals[i] += __shfl_down_sync(0xffffffffu, vals[i], o);
    }
    int w = threadIdx.x >> 5, l = threadIdx.x & 31;
    if (l == 0) {
        #pragma unroll
        for (int i = 0; i < NV; i++) red[i * 16 + w] = vals[i];
    }
    __syncthreads();
    if (threadIdx.x < 32) {
        #pragma unroll
        for (int i = 0; i < NV; i++) {
            float x = (l < NWARP) ? red[i * 16 + l] : 0.0f;
            #pragma unroll
            for (int o = 8; o > 0; o >>= 1)
                x += __shfl_down_sync(0xffffffffu, x, o);
            vals[i] = x;
        }
    }
    __syncthreads();
}

// 32-value 5-round multi-value butterfly (R6-verified): lane L ends with
// the fully-reduced value of index L.
__device__ __forceinline__ void butterfly32(float* vals, int lane) {
    #pragma unroll
    for (int h = 16; h >= 1; h >>= 1) {
        bool up = (lane & h) != 0;
        #pragma unroll
        for (int i = 0; i < h; i++) {
            float keep = up ? vals[i + h] : vals[i];
            float send = up ? vals[i]     : vals[i + h];
            vals[i] = keep + __shfl_xor_sync(0xffffffffu, send, h);
        }
    }
}

// ---------------- Kernel A: streaming GEMM, 32 warps/SM ----------------
__global__ void __launch_bounds__(ANTHR, 4)
mg_gemm(const float* __restrict__ img,
        const float* __restrict__ txt) {
    // txtP float4 at index jj*256 + dd*64 + h*32 + ln (R6-verified layout):
    //   = { txt_v(4h+0)[d], .., txt_v(4h+3)[d] }, d = jj*128 + ln*4 + dd,
    //   txt_v(v)[d] = txt[((v&3)*2 + (v>>2))*D + d]
    __shared__ float4 txtP[2048];

    const int tid  = threadIdx.x;
    const int lane = tid & 31;
    const int wid  = tid >> 5;                 // 0..7

    for (int f = tid; f < 2048; f += ANTHR) {
        int jj = f >> 8, rem = f & 255, u = rem >> 5, ln = rem & 31;
        int dd = u >> 1, h = u & 1;
        int d = jj * 128 + ln * 4 + dd;
        float4 val;
        val.x = txt[(0 * 2 + h) * D_DIM + d];
        val.y = txt[(1 * 2 + h) * D_DIM + d];
        val.z = txt[(2 * 2 + h) * D_DIM + d];
        val.w = txt[(3 * 2 + h) * D_DIM + d];
        txtP[f] = val;
    }
    __syncthreads();

    const ulonglong2* ts2 = reinterpret_cast<const ulonglong2*>(txtP);

    // block owns group blockIdx.x (32 rows); warp owns 4 rows
    const int rowbase = blockIdx.x * 32 + wid * 4;
    const float4* gp = reinterpret_cast<const float4*>(img)
                     + (size_t)rowbase * 256 + lane;

    unsigned long long acc[4][4];
    #pragma unroll
    for (int g = 0; g < 4; g++)
        #pragma unroll
        for (int vp = 0; vp < 4; vp++) acc[g][vp] = 0ull;

    #pragma unroll 1
    for (int jj = 0; jj < 8; jj++) {
        float4 c[4];
        #pragma unroll
        for (int g = 0; g < 4; g++)
            c[g] = __ldcs(gp + g * 256 + jj * 32);

        #pragma unroll
        for (int dd = 0; dd < 4; dd++) {
            ulonglong2 tvA = ts2[jj * 256 + dd * 64 + lane];       // v0..3
            ulonglong2 tvB = ts2[jj * 256 + dd * 64 + 32 + lane];  // v4..7
            #pragma unroll
            for (int g = 0; g < 4; g++) {
                float xv = (dd == 0) ? c[g].x : (dd == 1) ? c[g].y
                         : (dd == 2) ? c[g].z : c[g].w;
                unsigned long long xx;
                asm("mov.b64 %0, {%1, %1};" : "=l"(xx) : "f"(xv));
                asm("fma.rn.f32x2 %0, %1, %2, %0;" : "+l"(acc[g][0]) : "l"(xx), "l"(tvA.x));
                asm("fma.rn.f32x2 %0, %1, %2, %0;" : "+l"(acc[g][1]) : "l"(xx), "l"(tvA.y));
                asm("fma.rn.f32x2 %0, %1, %2, %0;" : "+l"(acc[g][2]) : "l"(xx), "l"(tvB.x));
                asm("fma.rn.f32x2 %0, %1, %2, %0;" : "+l"(acc[g][3]) : "l"(xx), "l"(tvB.y));
            }
        }
    }

    // unpack 32 partials (g*8 + vp*2 + {0,1}) -> butterfly -> lane L holds L
    float vals[32];
    #pragma unroll
    for (int g = 0; g < 4; g++)
        #pragma unroll
        for (int vp = 0; vp < 4; vp++) {
            float x, y;
            asm("mov.b64 {%0, %1}, %2;" : "=f"(x), "=f"(y) : "l"(acc[g][vp]));
            vals[g * 8 + vp * 2]     = x;
            vals[g * 8 + vp * 2 + 1] = y;
        }
    butterfly32(vals, lane);

    // lane L = (g = L>>3, v = L&7): 128B coalesced store per warp
    g_sim[(size_t)(rowbase + (lane >> 3)) * 8 + (lane & 7)] = vals[0];
}

// ---------------- Kernel B: persistent Sinkhorn tail ----------------
__global__ void __launch_bounds__(NTHR, 1)
mg_sink(const float* __restrict__ ls,
        float* __restrict__ out) {
    __shared__ float red[9 * 16];
    __shared__ float bc[9];

    const int tid  = threadIdx.x;
    const int lane = tid & 31;
    const int wid  = tid >> 5;

    const int rg = wid * NBLK + blockIdx.x;
    const bool active = (rg < NGROUPS);
    const int row = rg * 32 + lane;

    float simv[8] = {0.f, 0.f, 0.f, 0.f, 0.f, 0.f, 0.f, 0.f};
    if (active) {
        const float4* sp = reinterpret_cast<const float4*>(&g_sim[(size_t)row * 8]);
        float4 s0 = sp[0], s1 = sp[1];
        simv[0] = s0.x; simv[1] = s0.y; simv[2] = s0.z; simv[3] = s0.w;
        simv[4] = s1.x; simv[5] = s1.y; simv[6] = s1.z; simv[7] = s1.w;
    }

    float Kv[8];
    #pragma unroll
    for (int i = 0; i < 8; i++) Kv[i] = active ? expf((simv[i] - 1.0f) * 10.0f) : 0.0f;

    const float uu = 1.0f / (float)M_ROWS;
    float cm[8], cp[8];
    #pragma unroll
    for (int i = 0; i < 8; i++) { cm[i] = 1.0f; cp[i] = 1.0f; }

    unsigned mygen = 0;
    int t = 0;
    for (;;) {
        t++;
        float vals9[9];
        if (active) {
            float err = 0.0f;
            float rr[2];
            #pragma unroll
            for (int b = 0; b < 2; b++) {
                float s = 0.0f, s2 = 0.0f;
                #pragma unroll
                for (int n = 0; n < 4; n++) {
                    s  = fmaf(Kv[b * 4 + n], cm[b * 4 + n], s);
                    s2 = fmaf(Kv[b * 4 + n], cp[b * 4 + n], s2);
                }
                float r    = uu / s;
                float rold = (t == 1) ? 1.0f : uu / s2;   // r0 = ones
                rr[b] = r;
                err += fabsf(r - rold);
            }
            #pragma unroll
            for (int b = 0; b < 2; b++)
                #pragma unroll
                for (int n = 0; n < 4; n++)
                    vals9[b * 4 + n] = Kv[b * 4 + n] * rr[b];
            vals9[8] = err;
        } else {
            #pragma unroll
            for (int i = 0; i < 9; i++) vals9[i] = 0.0f;
        }

        block_reduce<9>(vals9, red);
        const int sl = t & 1;
        if (tid == 0) {
            #pragma unroll
            for (int i = 0; i < 9; i++) g_part[sl][blockIdx.x * 16 + i] = vals9[i];
        }
        grid_barrier(mygen);

        float pv[9];
        #pragma unroll
        for (int i = 0; i < 9; i++)
            pv[i] = (tid < NBLK) ? g_part[sl][tid * 16 + i] : 0.0f;
        block_reduce<9>(pv, red);
        if (tid == 0) {
            float e = pv[8] * (1.0f / (2.0f * (float)M_ROWS));
            #pragma unroll
            for (int i = 0; i < 8; i++) bc[i] = 0.25f / pv[i];   // v = 1/N
            bc[8] = (e < SINK_THRESH || t >= SINK_MAX_ITER) ? 1.0f : 0.0f;
        }
        __syncthreads();
        int stop = (bc[8] != 0.0f);
        #pragma unroll
        for (int i = 0; i < 8; i++) { cp[i] = cm[i]; cm[i] = bc[i]; }
        if (stop) break;
    }

    float ov[2] = {0.0f, 0.0f};
    if (active) {
        #pragma unroll
        for (int b = 0; b < 2; b++) {
            float s = 0.0f, a = 0.0f;
            #pragma unroll
            for (int n = 0; n < 4; n++) {
                s = fmaf(Kv[b * 4 + n], cp[b * 4 + n], s);
                a = fmaf(cm[b * 4 + n] * Kv[b * 4 + n], simv[b * 4 + n], a);
            }
            ov[b] += (uu / s) * a;
        }
    }
    block_reduce<2>(ov, red);
    const int slf = (t + 1) & 1;
    if (tid == 0) {
        g_part[slf][blockIdx.x * 16 + 0] = ov[0];
        g_part[slf][blockIdx.x * 16 + 1] = ov[1];
    }
    grid_barrier(mygen);
    if (blockIdx.x == 0) {
        float pv[2];
        pv[0] = (tid < NBLK) ? g_part[slf][tid * 16 + 0] : 0.0f;
        pv[1] = (tid < NBLK) ? g_part[slf][tid * 16 + 1] : 0.0f;
        block_reduce<2>(pv, red);
        if (tid == 0) {
            float sc = expf(ls[0]);
            out[0] = sc * pv[0];
            out[1] = sc * pv[1];
        }
    }
}

extern "C" void kernel_launch(void* const* d_in, const int* in_sizes, int n_in,
                              void* d_out, int out_size) {
    const float* img = (const float*)d_in[0];
    const float* txt = (const float*)d_in[1];
    const float* ls  = (const float*)d_in[2];
    float* out = (float*)d_out;
    (void)in_sizes; (void)n_in; (void)out_size;

    mg_init<<<1, 1>>>();
    mg_gemm<<<NGROUPS, ANTHR>>>(img, txt);
    mg_sink<<<NBLK, NTHR>>>(ls, out);
}

// round 12
// speedup vs baseline: 1.0815x; 1.0815x over previous
#include <cuda_runtime.h>
#include <cstdint>

// ---------------------------------------------------------------------------
// MGPATH Sinkhorn-OT head, fused persistent kernel. R12:
// d-pair-packed f32x2 accumulators (img float4 consumed as natural u64
// halves -> ZERO dup movs), plain v-major txt smem (R2-verified layout),
// depth-2 x 4-row register prefetch, no init kernel (self-sync g_gen).
// Butterfly/transpose/Sinkhorn machinery R6-verified verbatim.
// ---------------------------------------------------------------------------

#define M_ROWS 65536
#define D_DIM  1024
#define NBLK   148
#define NTHR   448
#define NWARP  14
#define NGROUPS 2048            // 65536 rows / 32 rows-per-warp-group
#define NPASS  8                // 4 rows per pass
#define SINK_MAX_ITER 100
#define SINK_THRESH 0.01f

__device__ volatile float    g_part[2][NBLK * 16];
__device__ unsigned          g_cnt = 0u;
__device__ volatile unsigned g_gen = 0u;

// sense-reversing grid barrier; all NBLK blocks co-resident (1/SM, 148 SMs).
// mygen is seeded from g_gen at kernel entry (safe: g_gen can only advance
// after all 148 blocks have arrived at a barrier, i.e. after all entry reads).
__device__ __forceinline__ void grid_barrier(unsigned &mygen) {
    __syncthreads();
    if (threadIdx.x == 0) {
        __threadfence();
        unsigned prev = atomicAdd(&g_cnt, 1u);
        if (prev == NBLK - 1) {
            g_cnt = 0u;
            __threadfence();
            g_gen = mygen + 1u;
        } else {
            while (g_gen == mygen) { __nanosleep(32); }
        }
        __threadfence();
    }
    __syncthreads();
    mygen++;
}

template <int NV>
__device__ __forceinline__ void block_reduce(float* vals, float* red) {
    #pragma unroll
    for (int i = 0; i < NV; i++) {
        #pragma unroll
        for (int o = 16; o > 0; o >>= 1)
            vals[i] += __shfl_down_sync(0xffffffffu, vals[i], o);
    }
    int w = threadIdx.x >> 5, l = threadIdx.x & 31;
    if (l == 0) {
        #pragma unroll
        for (int i = 0; i < NV; i++) red[i * 16 + w] = vals[i];
    }
    __syncthreads();
    if (threadIdx.x < 32) {
        #pragma unroll
        for (int i = 0; i < NV; i++) {
            float x = (l < NWARP) ? red[i * 16 + l] : 0.0f;
            #pragma unroll
            for (int o = 8; o > 0; o >>= 1)
                x += __shfl_down_sync(0xffffffffu, x, o);
            vals[i] = x;
        }
    }
    __syncthreads();
}

// 32-value 5-round multi-value butterfly (R6-verified): lane L ends with
// the fully-reduced value of index L.
__device__ __forceinline__ void butterfly32(float* vals, int lane) {
    #pragma unroll
    for (int h = 16; h >= 1; h >>= 1) {
        bool up = (lane & h) != 0;
        #pragma unroll
        for (int i = 0; i < h; i++) {
            float keep = up ? vals[i + h] : vals[i];
            float send = up ? vals[i]     : vals[i + h];
            vals[i] = keep + __shfl_xor_sync(0xffffffffu, send, h);
        }
    }
}

__global__ void __launch_bounds__(NTHR, 1)
mg_fused(const float* __restrict__ img,
         const float* __restrict__ txt,
         const float* __restrict__ ls,
         float* __restrict__ out) {
    // v-major txt (R2-verified): txtS[v*1024 + d], v = c*4 + n,
    // value = txt[(n*2+c)*D + d]
    __shared__ float txtS[8 * D_DIM];
    __shared__ float simP[NWARP * 32];
    __shared__ float red[9 * 16];
    __shared__ float bc[9];

    const int tid  = threadIdx.x;
    const int lane = tid & 31;
    const int wid  = tid >> 5;

    unsigned mygen = g_gen;     // self-sync generation base (see grid_barrier)

    for (int i = tid; i < 8 * D_DIM; i += NTHR) {
        int v = i >> 10, d = i & 1023;
        int n = v & 3, c = v >> 2;
        txtS[i] = txt[(n * 2 + c) * D_DIM + d];
    }
    __syncthreads();

    // warp-slot owns one 32-row group
    const int rg = wid * NBLK + blockIdx.x;
    const bool active = (rg < NGROUPS);

    const ulonglong2* ts2 = reinterpret_cast<const ulonglong2*>(txtS);

    float simv[8] = {0.f, 0.f, 0.f, 0.f, 0.f, 0.f, 0.f, 0.f};

    if (active) {
        // lane-local base: group start + lane's 16B column (u64x2 view)
        const ulonglong2* gp = reinterpret_cast<const ulonglong2*>(img)
                             + (size_t)rg * 32 * 256 + lane;

        // depth-2 double buffer over linear steps s = pass*8 + jj (4 rows);
        // step s loads rows (s>>3)*4..+3, chunk (s&7).
        ulonglong2 buf[2][4];
        #pragma unroll
        for (int g = 0; g < 4; g++) buf[0][g] = __ldcs(gp + g * 256);
        #pragma unroll
        for (int g = 0; g < 4; g++) buf[1][g] = __ldcs(gp + g * 256 + 32);

        #pragma unroll 1
        for (int pass = 0; pass < NPASS; pass++) {
            // acc[row][v] packs (d-even, d-odd) partials in f32x2
            unsigned long long acc[4][8];
            #pragma unroll
            for (int g = 0; g < 4; g++)
                #pragma unroll
                for (int v = 0; v < 8; v++) acc[g][v] = 0ull;

            #pragma unroll
            for (int jj = 0; jj < 8; jj++) {
                const int p = jj & 1;
                ulonglong2 c[4];
                #pragma unroll
                for (int g = 0; g < 4; g++) c[g] = buf[p][g];

                // refill this parity slot with step s+2
                int s = pass * 8 + jj + 2;
                if (s < NPASS * 8) {
                    int tp = s >> 3, tj = s & 7;
                    #pragma unroll
                    for (int g = 0; g < 4; g++)
                        buf[p][g] = __ldcs(gp + (size_t)(tp * 4 + g) * 256 + tj * 32);
                }

                #pragma unroll
                for (int v = 0; v < 8; v++) {
                    ulonglong2 tv = ts2[v * 256 + jj * 32 + lane]; // txt_v[d..d+3]
                    #pragma unroll
                    for (int g = 0; g < 4; g++) {
                        asm("fma.rn.f32x2 %0, %1, %2, %0;" : "+l"(acc[g][v]) : "l"(c[g].x), "l"(tv.x));
                        asm("fma.rn.f32x2 %0, %1, %2, %0;" : "+l"(acc[g][v]) : "l"(c[g].y), "l"(tv.y));
                    }
                }
            }

            // unpack: vals[g*8+v] = lo(acc)+hi(acc)  (even-d + odd-d partials)
            float vals[32];
            #pragma unroll
            for (int g = 0; g < 4; g++)
                #pragma unroll
                for (int v = 0; v < 8; v++) {
                    float x, y;
                    asm("mov.b64 {%0, %1}, %2;" : "=f"(x), "=f"(y) : "l"(acc[g][v]));
                    vals[g * 8 + v] = x + y;
                }
            butterfly32(vals, lane);

            // transpose via smem slab (R6-verified): row (pass*4+g) gets its 8 v's
            simP[wid * 32 + lane] = vals[0];
            __syncwarp();
            if ((lane >> 2) == pass) {
                int base = wid * 32 + (lane & 3) * 8;
                float4 s0 = *reinterpret_cast<float4*>(&simP[base]);
                float4 s1 = *reinterpret_cast<float4*>(&simP[base + 4]);
                simv[0] = s0.x; simv[1] = s0.y; simv[2] = s0.z; simv[3] = s0.w;
                simv[4] = s1.x; simv[5] = s1.y; simv[6] = s1.z; simv[7] = s1.w;
            }
            __syncwarp();
        }
    }

    // K = exp(-(1 - sim)/0.1); lane owns row rg*32 + lane
    float Kv[8];
    #pragma unroll
    for (int i = 0; i < 8; i++) Kv[i] = active ? expf((simv[i] - 1.0f) * 10.0f) : 0.0f;

    const float uu = 1.0f / (float)M_ROWS;
    float cm[8], cp[8];
    #pragma unroll
    for (int i = 0; i < 8; i++) { cm[i] = 1.0f; cp[i] = 1.0f; }

    // ---- Sinkhorn loop: 1 grid barrier per iteration (R6-verified) ----
    int t = 0;
    for (;;) {
        t++;
        float vals9[9];
        if (active) {
            float err = 0.0f;
            float rr[2];
            #pragma unroll
            for (int b = 0; b < 2; b++) {
                float s = 0.0f, s2 = 0.0f;
                #pragma unroll
                for (int n = 0; n < 4; n++) {
                    s  = fmaf(Kv[b * 4 + n], cm[b * 4 + n], s);
                    s2 = fmaf(Kv[b * 4 + n], cp[b * 4 + n], s2);
                }
                float r    = uu / s;
                float rold = (t == 1) ? 1.0f : uu / s2;   // r0 = ones
                rr[b] = r;
                err += fabsf(r - rold);
            }
            #pragma unroll
            for (int b = 0; b < 2; b++)
                #pragma unroll
                for (int n = 0; n < 4; n++)
                    vals9[b * 4 + n] = Kv[b * 4 + n] * rr[b];
            vals9[8] = err;
        } else {
            #pragma unroll
            for (int i = 0; i < 9; i++) vals9[i] = 0.0f;
        }

        block_reduce<9>(vals9, red);
        const int sl = t & 1;
        if (tid == 0) {
            #pragma unroll
            for (int i = 0; i < 9; i++) g_part[sl][blockIdx.x * 16 + i] = vals9[i];
        }
        grid_barrier(mygen);

        // every block reduces all partials (identical result everywhere)
        float pv[9];
        #pragma unroll
        for (int i = 0; i < 9; i++)
            pv[i] = (tid < NBLK) ? g_part[sl][tid * 16 + i] : 0.0f;
        block_reduce<9>(pv, red);
        if (tid == 0) {
            float e = pv[8] * (1.0f / (2.0f * (float)M_ROWS));
            #pragma unroll
            for (int i = 0; i < 8; i++) bc[i] = 0.25f / pv[i];   // v = 1/N
            bc[8] = (e < SINK_THRESH || t >= SINK_MAX_ITER) ? 1.0f : 0.0f;
        }
        __syncthreads();
        int stop = (bc[8] != 0.0f);
        #pragma unroll
        for (int i = 0; i < 8; i++) { cp[i] = cm[i]; cm[i] = bc[i]; }
        if (stop) break;
    }

    // ---- final: sim_op[b] = sum_m r_T[m] * sum_n c_T[n] K[m,n] sim[m,n] ----
    float ov[2] = {0.0f, 0.0f};
    if (active) {
        #pragma unroll
        for (int b = 0; b < 2; b++) {
            float s = 0.0f, a = 0.0f;
            #pragma unroll
            for (int n = 0; n < 4; n++) {
                s = fmaf(Kv[b * 4 + n], cp[b * 4 + n], s);
                a = fmaf(cm[b * 4 + n] * Kv[b * 4 + n], simv[b * 4 + n], a);
            }
            ov[b] += (uu / s) * a;
        }
    }
    block_reduce<2>(ov, red);
    const int slf = (t + 1) & 1;
    if (tid == 0) {
        g_part[slf][blockIdx.x * 16 + 0] = ov[0];
        g_part[slf][blockIdx.x * 16 + 1] = ov[1];
    }
    grid_barrier(mygen);
    if (blockIdx.x == 0) {
        float pv[2];
        pv[0] = (tid < NBLK) ? g_part[slf][tid * 16 + 0] : 0.0f;
        pv[1] = (tid < NBLK) ? g_part[slf][tid * 16 + 1] : 0.0f;
        block_reduce<2>(pv, red);
        if (tid == 0) {
            float sc = expf(ls[0]);
            out[0] = sc * pv[0];
            out[1] = sc * pv[1];
        }
    }
}

extern "C" void kernel_launch(void* const* d_in, const int* in_sizes, int n_in,
                              void* d_out, int out_size) {
    const float* img = (const float*)d_in[0];
    const float* txt = (const float*)d_in[1];
    const float* ls  = (const float*)d_in[2];
    float* out = (float*)d_out;
    (void)in_sizes; (void)n_in; (void)out_size;

    mg_fused<<<NBLK, NTHR>>>(img, txt, ls, out);
}

// round 13
// speedup vs baseline: 1.1212x; 1.0367x over previous
#include <cuda_runtime.h>
#include <cstdint>

// ---------------------------------------------------------------------------
// MGPATH Sinkhorn-OT head, fused persistent kernel. R13 = R6 GEMM (proven
// fastest: v-pair-packed f32x2 acc, depth-4 circular prefetch, 4 rows/pass)
// + R12 init-free self-sync barrier and 1-barrier-per-iteration Sinkhorn.
// ---------------------------------------------------------------------------

#define M_ROWS 65536
#define D_DIM  1024
#define NBLK   148
#define NTHR   448
#define NWARP  14
#define NGROUPS 2048            // 65536 rows / 32 rows-per-warp-group
#define NPASS  8                // 4 rows per pass
#define SINK_MAX_ITER 100
#define SINK_THRESH 0.01f

__device__ volatile float    g_part[2][NBLK * 16];
__device__ unsigned          g_cnt = 0u;
__device__ volatile unsigned g_gen = 0u;

// sense-reversing grid barrier; all NBLK blocks co-resident (1/SM, 148 SMs).
// mygen seeded from g_gen at entry (R12-verified): g_gen can only advance
// after all 148 blocks reach a barrier, i.e. after all entry reads.
__device__ __forceinline__ void grid_barrier(unsigned &mygen) {
    __syncthreads();
    if (threadIdx.x == 0) {
        __threadfence();
        unsigned prev = atomicAdd(&g_cnt, 1u);
        if (prev == NBLK - 1) {
            g_cnt = 0u;
            __threadfence();
            g_gen = mygen + 1u;
        } else {
            while (g_gen == mygen) { __nanosleep(32); }
        }
        __threadfence();
    }
    __syncthreads();
    mygen++;
}

template <int NV>
__device__ __forceinline__ void block_reduce(float* vals, float* red) {
    #pragma unroll
    for (int i = 0; i < NV; i++) {
        #pragma unroll
        for (int o = 16; o > 0; o >>= 1)
            vals[i] += __shfl_down_sync(0xffffffffu, vals[i], o);
    }
    int w = threadIdx.x >> 5, l = threadIdx.x & 31;
    if (l == 0) {
        #pragma unroll
        for (int i = 0; i < NV; i++) red[i * 16 + w] = vals[i];
    }
    __syncthreads();
    if (threadIdx.x < 32) {
        #pragma unroll
        for (int i = 0; i < NV; i++) {
            float x = (l < NWARP) ? red[i * 16 + l] : 0.0f;
            #pragma unroll
            for (int o = 8; o > 0; o >>= 1)
                x += __shfl_down_sync(0xffffffffu, x, o);
            vals[i] = x;
        }
    }
    __syncthreads();
}

// 32-value 5-round multi-value butterfly (R6-verified): lane L ends with
// the fully-reduced value of index L.
__device__ __forceinline__ void butterfly32(float* vals, int lane) {
    #pragma unroll
    for (int h = 16; h >= 1; h >>= 1) {
        bool up = (lane & h) != 0;
        #pragma unroll
        for (int i = 0; i < h; i++) {
            float keep = up ? vals[i + h] : vals[i];
            float send = up ? vals[i]     : vals[i + h];
            vals[i] = keep + __shfl_xor_sync(0xffffffffu, send, h);
        }
    }
}

__global__ void __launch_bounds__(NTHR, 1)
mg_fused(const float* __restrict__ img,
         const float* __restrict__ txt,
         const float* __restrict__ ls,
         float* __restrict__ out) {
    // txtP float4 at index jj*256 + dd*64 + h*32 + ln (R6-verified layout):
    //   = { txt_v(4h+0)[d], .., txt_v(4h+3)[d] }, d = jj*128 + ln*4 + dd,
    //   txt_v(v)[d] = txt[((v&3)*2 + (v>>2))*D + d]
    __shared__ float4 txtP[2048];
    __shared__ float  simP[NWARP * 32];
    __shared__ float  red[9 * 16];
    __shared__ float  bc[9];

    const int tid  = threadIdx.x;
    const int lane = tid & 31;
    const int wid  = tid >> 5;

    unsigned mygen = g_gen;     // self-sync generation base

    for (int f = tid; f < 2048; f += NTHR) {
        int jj = f >> 8, rem = f & 255, u = rem >> 5, ln = rem & 31;
        int dd = u >> 1, h = u & 1;
        int d = jj * 128 + ln * 4 + dd;
        float4 val;
        val.x = txt[(0 * 2 + h) * D_DIM + d];   // n=0, c=h
        val.y = txt[(1 * 2 + h) * D_DIM + d];   // n=1
        val.z = txt[(2 * 2 + h) * D_DIM + d];   // n=2
        val.w = txt[(3 * 2 + h) * D_DIM + d];   // n=3
        txtP[f] = val;
    }
    __syncthreads();

    // warp-slot owns one 32-row group
    const int rg = wid * NBLK + blockIdx.x;
    const bool active = (rg < NGROUPS);

    const ulonglong2* ts2 = reinterpret_cast<const ulonglong2*>(txtP);

    float simv[8] = {0.f, 0.f, 0.f, 0.f, 0.f, 0.f, 0.f, 0.f};

    if (active) {
        const float4* gp = reinterpret_cast<const float4*>(img)
                         + (size_t)rg * 32 * 256 + lane;

        // depth-4 circular buffer over linear steps s = pass*8 + jj, 4 rows
        float4 buf[4][4];
        #pragma unroll
        for (int s = 0; s < 4; s++)
            #pragma unroll
            for (int g = 0; g < 4; g++)
                buf[s][g] = __ldcs(gp + g * 256 + s * 32);   // pass 0

        #pragma unroll 1
        for (int pass = 0; pass < NPASS; pass++) {
            unsigned long long acc[4][4];
            #pragma unroll
            for (int g = 0; g < 4; g++)
                #pragma unroll
                for (int vp = 0; vp < 4; vp++) acc[g][vp] = 0ull;

            #pragma unroll
            for (int jj = 0; jj < 8; jj++) {
                float4 c[4];
                #pragma unroll
                for (int g = 0; g < 4; g++) c[g] = buf[jj & 3][g];

                // prefetch step s+4 into the vacated circular slot
                if (pass < NPASS - 1 || jj < 4) {
                    int s  = pass * 8 + jj + 4;
                    int tp = s >> 3, tj = s & 7;
                    #pragma unroll
                    for (int g = 0; g < 4; g++)
                        buf[jj & 3][g] = __ldcs(gp + (tp * 4 + g) * 256 + tj * 32);
                }

                #pragma unroll
                for (int dd = 0; dd < 4; dd++) {
                    ulonglong2 tvA = ts2[jj * 256 + dd * 64 + lane];       // v0..3
                    ulonglong2 tvB = ts2[jj * 256 + dd * 64 + 32 + lane];  // v4..7
                    #pragma unroll
                    for (int g = 0; g < 4; g++) {
                        float xv = (dd == 0) ? c[g].x : (dd == 1) ? c[g].y
                                 : (dd == 2) ? c[g].z : c[g].w;
                        unsigned long long xx;
                        asm("mov.b64 %0, {%1, %1};" : "=l"(xx) : "f"(xv));
                        asm("fma.rn.f32x2 %0, %1, %2, %0;" : "+l"(acc[g][0]) : "l"(xx), "l"(tvA.x));
                        asm("fma.rn.f32x2 %0, %1, %2, %0;" : "+l"(acc[g][1]) : "l"(xx), "l"(tvA.y));
                        asm("fma.rn.f32x2 %0, %1, %2, %0;" : "+l"(acc[g][2]) : "l"(xx), "l"(tvB.x));
                        asm("fma.rn.f32x2 %0, %1, %2, %0;" : "+l"(acc[g][3]) : "l"(xx), "l"(tvB.y));
                    }
                }
            }

            // unpack 32 partials: vals[g*8 + vp*2 + {0,1}] = (lo,hi) of acc
            float vals[32];
            #pragma unroll
            for (int g = 0; g < 4; g++)
                #pragma unroll
                for (int vp = 0; vp < 4; vp++) {
                    float x, y;
                    asm("mov.b64 {%0, %1}, %2;" : "=f"(x), "=f"(y) : "l"(acc[g][vp]));
                    vals[g * 8 + vp * 2]     = x;
                    vals[g * 8 + vp * 2 + 1] = y;
                }
            butterfly32(vals, lane);

            // transpose via smem slab: row (pass*4+g) gets its 8 v's
            simP[wid * 32 + lane] = vals[0];
            __syncwarp();
            if ((lane >> 2) == pass) {
                int base = wid * 32 + (lane & 3) * 8;
                float4 s0 = *reinterpret_cast<float4*>(&simP[base]);
                float4 s1 = *reinterpret_cast<float4*>(&simP[base + 4]);
                simv[0] = s0.x; simv[1] = s0.y; simv[2] = s0.z; simv[3] = s0.w;
                simv[4] = s1.x; simv[5] = s1.y; simv[6] = s1.z; simv[7] = s1.w;
            }
            __syncwarp();
        }
    }

    // K = exp(-(1 - sim)/0.1); lane owns row rg*32 + lane
    float Kv[8];
    #pragma unroll
    for (int i = 0; i < 8; i++) Kv[i] = active ? expf((simv[i] - 1.0f) * 10.0f) : 0.0f;

    const float uu = 1.0f / (float)M_ROWS;
    float cm[8], cp[8];
    #pragma unroll
    for (int i = 0; i < 8; i++) { cm[i] = 1.0f; cp[i] = 1.0f; }

    // ---- Sinkhorn loop: 1 grid barrier per iteration (R12-verified) ----
    int t = 0;
    for (;;) {
        t++;
        float vals9[9];
        if (active) {
            float err = 0.0f;
            float rr[2];
            #pragma unroll
            for (int b = 0; b < 2; b++) {
                float s = 0.0f, s2 = 0.0f;
                #pragma unroll
                for (int n = 0; n < 4; n++) {
                    s  = fmaf(Kv[b * 4 + n], cm[b * 4 + n], s);
                    s2 = fmaf(Kv[b * 4 + n], cp[b * 4 + n], s2);
                }
                float r    = uu / s;
                float rold = (t == 1) ? 1.0f : uu / s2;   // r0 = ones
                rr[b] = r;
                err += fabsf(r - rold);
            }
            #pragma unroll
            for (int b = 0; b < 2; b++)
                #pragma unroll
                for (int n = 0; n < 4; n++)
                    vals9[b * 4 + n] = Kv[b * 4 + n] * rr[b];
            vals9[8] = err;
        } else {
            #pragma unroll
            for (int i = 0; i < 9; i++) vals9[i] = 0.0f;
        }

        block_reduce<9>(vals9, red);
        const int sl = t & 1;
        if (tid == 0) {
            #pragma unroll
            for (int i = 0; i < 9; i++) g_part[sl][blockIdx.x * 16 + i] = vals9[i];
        }
        grid_barrier(mygen);

        // every block reduces all partials (identical result everywhere)
        float pv[9];
        #pragma unroll
        for (int i = 0; i < 9; i++)
            pv[i] = (tid < NBLK) ? g_part[sl][tid * 16 + i] : 0.0f;
        block_reduce<9>(pv, red);
        if (tid == 0) {
            float e = pv[8] * (1.0f / (2.0f * (float)M_ROWS));
            #pragma unroll
            for (int i = 0; i < 8; i++) bc[i] = 0.25f / pv[i];   // v = 1/N
            bc[8] = (e < SINK_THRESH || t >= SINK_MAX_ITER) ? 1.0f : 0.0f;
        }
        __syncthreads();
        int stop = (bc[8] != 0.0f);
        #pragma unroll
        for (int i = 0; i < 8; i++) { cp[i] = cm[i]; cm[i] = bc[i]; }
        if (stop) break;
    }

    // ---- final: sim_op[b] = sum_m r_T[m] * sum_n c_T[n] K[m,n] sim[m,n] ----
    float ov[2] = {0.0f, 0.0f};
    if (active) {
        #pragma unroll
        for (int b = 0; b < 2; b++) {
            float s = 0.0f, a = 0.0f;
            #pragma unroll
            for (int n = 0; n < 4; n++) {
                s = fmaf(Kv[b * 4 + n], cp[b * 4 + n], s);
                a = fmaf(cm[b * 4 + n] * Kv[b * 4 + n], simv[b * 4 + n], a);
            }
            ov[b] += (uu / s) * a;
        }
    }
    block_reduce<2>(ov, red);
    const int slf = (t + 1) & 1;
    if (tid == 0) {
        g_part[slf][blockIdx.x * 16 + 0] = ov[0];
        g_part[slf][blockIdx.x * 16 + 1] = ov[1];
    }
    grid_barrier(mygen);
    if (blockIdx.x == 0) {
        float pv[2];
        pv[0] = (tid < NBLK) ? g_part[slf][tid * 16 + 0] : 0.0f;
        pv[1] = (tid < NBLK) ? g_part[slf][tid * 16 + 1] : 0.0f;
        block_reduce<2>(pv, red);
        if (tid == 0) {
            float sc = expf(ls[0]);
            out[0] = sc * pv[0];
            out[1] = sc * pv[1];
        }
    }
}

extern "C" void kernel_launch(void* const* d_in, const int* in_sizes, int n_in,
                              void* d_out, int out_size) {
    const float* img = (const float*)d_in[0];
    const float* txt = (const float*)d_in[1];
    const float* ls  = (const float*)d_in[2];
    float* out = (float*)d_out;
    (void)in_sizes; (void)n_in; (void)out_size;

    mg_fused<<<NBLK, NTHR>>>(img, txt, ls, out);
}

// round 14
// speedup vs baseline: 1.1610x; 1.0355x over previous
#include <cuda_runtime.h>
#include <cstdint>

// ---------------------------------------------------------------------------
// MGPATH Sinkhorn-OT head, fused persistent kernel. R14 = R13 math with the
// img feed moved to the bulk-async (TMA) engine: warp-private 4-slot x 2KB
// smem ring filled by cp.async.bulk (bypasses the L1tex MSHR window that
// pins LDG/LDGSTS at ~4 TB/s), consumed via conflict-free LDS.128.
// Butterfly/transpose/Sinkhorn machinery R6/R12-verified verbatim.
// ---------------------------------------------------------------------------

#define M_ROWS 65536
#define D_DIM  1024
#define NBLK   148
#define NTHR   448
#define NWARP  14
#define NGROUPS 2048            // 65536 rows / 32 rows-per-warp-group
#define NPASS  8                // 4 rows per pass, 32 steps total
#define RING_DEPTH 4
#define SLOT_BYTES 2048         // one step: 4 rows x 512B
#define RING_BYTES (RING_DEPTH * SLOT_BYTES)
#define SINK_MAX_ITER 100
#define SINK_THRESH 0.01f

// dynamic smem layout (bytes)
#define SMEM_TXT   0                                     // 32768
#define SMEM_RING  32768
#define SMEM_SIMP  (SMEM_RING + NWARP * RING_BYTES)      // 147456
#define SMEM_RED   (SMEM_SIMP + NWARP * 32 * 4)          // 149248
#define SMEM_BC    (SMEM_RED + 9 * 16 * 4)               // 149824
#define SMEM_MBAR  (SMEM_BC + 64)                        // 149888
#define SMEM_TOTAL (SMEM_MBAR + NWARP * RING_DEPTH * 8 + 64)

__device__ volatile float    g_part[2][NBLK * 16];
__device__ unsigned          g_cnt = 0u;
__device__ volatile unsigned g_gen = 0u;

// sense-reversing grid barrier; all NBLK blocks co-resident (1/SM, 148 SMs).
// mygen seeded from g_gen at entry (R12-verified).
__device__ __forceinline__ void grid_barrier(unsigned &mygen) {
    __syncthreads();
    if (threadIdx.x == 0) {
        __threadfence();
        unsigned prev = atomicAdd(&g_cnt, 1u);
        if (prev == NBLK - 1) {
            g_cnt = 0u;
            __threadfence();
            g_gen = mygen + 1u;
        } else {
            while (g_gen == mygen) { __nanosleep(32); }
        }
        __threadfence();
    }
    __syncthreads();
    mygen++;
}

template <int NV>
__device__ __forceinline__ void block_reduce(float* vals, float* red) {
    #pragma unroll
    for (int i = 0; i < NV; i++) {
        #pragma unroll
        for (int o = 16; o > 0; o >>= 1)
            vals[i] += __shfl_down_sync(0xffffffffu, vals[i], o);
    }
    int w = threadIdx.x >> 5, l = threadIdx.x & 31;
    if (l == 0) {
        #pragma unroll
        for (int i = 0; i < NV; i++) red[i * 16 + w] = vals[i];
    }
    __syncthreads();
    if (threadIdx.x < 32) {
        #pragma unroll
        for (int i = 0; i < NV; i++) {
            float x = (l < NWARP) ? red[i * 16 + l] : 0.0f;
            #pragma unroll
            for (int o = 8; o > 0; o >>= 1)
                x += __shfl_down_sync(0xffffffffu, x, o);
            vals[i] = x;
        }
    }
    __syncthreads();
}

// 32-value 5-round multi-value butterfly (R6-verified): lane L ends with
// the fully-reduced value of index L.
__device__ __forceinline__ void butterfly32(float* vals, int lane) {
    #pragma unroll
    for (int h = 16; h >= 1; h >>= 1) {
        bool up = (lane & h) != 0;
        #pragma unroll
        for (int i = 0; i < h; i++) {
            float keep = up ? vals[i + h] : vals[i];
            float send = up ? vals[i]     : vals[i + h];
            vals[i] = keep + __shfl_xor_sync(0xffffffffu, send, h);
        }
    }
}

__device__ __forceinline__ unsigned int smem_u32(const void* p) {
    return (unsigned int)__cvta_generic_to_shared(p);
}

__device__ __forceinline__ void mbar_wait_parity(unsigned int mb, unsigned int par) {
    unsigned int done;
    asm volatile(
        "{\n\t.reg .pred p;\n\t"
        "mbarrier.try_wait.parity.acquire.cta.shared::cta.b64 p, [%1], %2;\n\t"
        "selp.b32 %0, 1, 0, p;\n\t}"
        : "=r"(done) : "r"(mb), "r"(par) : "memory");
    while (!done) {
        asm volatile(
            "{\n\t.reg .pred p;\n\t"
            "mbarrier.try_wait.parity.acquire.cta.shared::cta.b64 p, [%1], %2, 0x989680;\n\t"
            "selp.b32 %0, 1, 0, p;\n\t}"
            : "=r"(done) : "r"(mb), "r"(par) : "memory");
    }
}

__global__ void __launch_bounds__(NTHR, 1)
mg_fused(const float* __restrict__ img,
         const float* __restrict__ txt,
         const float* __restrict__ ls,
         float* __restrict__ out) {
    extern __shared__ char smem[];
    float4* txtP = reinterpret_cast<float4*>(smem + SMEM_TXT);
    float*  simP = reinterpret_cast<float*>(smem + SMEM_SIMP);
    float*  red  = reinterpret_cast<float*>(smem + SMEM_RED);
    float*  bc   = reinterpret_cast<float*>(smem + SMEM_BC);

    const int tid  = threadIdx.x;
    const int lane = tid & 31;
    const int wid  = tid >> 5;

    unsigned mygen = g_gen;     // self-sync generation base (R12-verified)

    // txtP float4 at index jj*256 + dd*64 + h*32 + ln (R6-verified layout)
    for (int f = tid; f < 2048; f += NTHR) {
        int jj = f >> 8, rem = f & 255, u = rem >> 5, ln = rem & 31;
        int dd = u >> 1, h = u & 1;
        int d = jj * 128 + ln * 4 + dd;
        float4 val;
        val.x = txt[(0 * 2 + h) * D_DIM + d];
        val.y = txt[(1 * 2 + h) * D_DIM + d];
        val.z = txt[(2 * 2 + h) * D_DIM + d];
        val.w = txt[(3 * 2 + h) * D_DIM + d];
        txtP[f] = val;
    }
    __syncthreads();

    // warp-slot owns one 32-row group
    const int rg = wid * NBLK + blockIdx.x;
    const bool active = (rg < NGROUPS);

    const ulonglong2* ts2 = reinterpret_cast<const ulonglong2*>(txtP);

    float simv[8] = {0.f, 0.f, 0.f, 0.f, 0.f, 0.f, 0.f, 0.f};

    if (active) {
        // group base: 32 rows x 4KB each = 128KB contiguous
        const char* gbase = reinterpret_cast<const char*>(img)
                          + (size_t)rg * 32 * 4096;
        char* ring = smem + SMEM_RING + wid * RING_BYTES;
        const unsigned int ringU = smem_u32(ring);
        const unsigned int mbar0 = smem_u32(smem + SMEM_MBAR) + wid * (RING_DEPTH * 8);

        if (lane == 0) {
            #pragma unroll
            for (int s = 0; s < RING_DEPTH; s++)
                asm volatile("mbarrier.init.shared.b64 [%0], %1;"
                             :: "r"(mbar0 + s * 8), "r"(1) : "memory");
        }
        __syncwarp();

        // issue one step (4 row-slices of 512B) via the bulk-async engine
        auto issue_step = [&](int s) {
            int slot = s & (RING_DEPTH - 1);
            int tp = s >> 3, tj = s & 7;
            unsigned int mb = mbar0 + slot * 8;
            asm volatile("mbarrier.arrive.expect_tx.shared.b64 _, [%0], %1;"
                         :: "r"(mb), "r"(SLOT_BYTES) : "memory");
            unsigned int dst = ringU + slot * SLOT_BYTES;
            const char* src = gbase + (size_t)(tp * 4) * 4096 + tj * 512;
            #pragma unroll
            for (int g = 0; g < 4; g++)
                asm volatile(
                    "cp.async.bulk.shared::cta.global.mbarrier::complete_tx::bytes "
                    "[%0], [%1], %2, [%3];"
                    :: "r"(dst + g * 512), "l"(src + (size_t)g * 4096),
                       "r"(512), "r"(mb) : "memory");
        };

        if (lane == 0) {
            issue_step(0); issue_step(1); issue_step(2); issue_step(3);
        }

        #pragma unroll 1
        for (int pass = 0; pass < NPASS; pass++) {
            unsigned long long acc[4][4];
            #pragma unroll
            for (int g = 0; g < 4; g++)
                #pragma unroll
                for (int vp = 0; vp < 4; vp++) acc[g][vp] = 0ull;

            #pragma unroll
            for (int jj = 0; jj < 8; jj++) {
                const int step = pass * 8 + jj;
                const int slot = step & (RING_DEPTH - 1);
                const unsigned int par = (unsigned)((step >> 2) & 1);
                mbar_wait_parity(mbar0 + slot * 8, par);

                // consume: 4 rows' 16B slices, conflict-free LDS.128
                float4 c[4];
                const char* sb = ring + slot * SLOT_BYTES + lane * 16;
                #pragma unroll
                for (int g = 0; g < 4; g++)
                    c[g] = *reinterpret_cast<const float4*>(sb + g * 512);

                // refill the vacated slot with step+4 (bulk data lands >>
                // later than the just-issued LDS drain; .acquire wait orders
                // the next consume after those writes)
                if (lane == 0 && step + 4 < NPASS * 8) issue_step(step + 4);

                #pragma unroll
                for (int dd = 0; dd < 4; dd++) {
                    ulonglong2 tvA = ts2[jj * 256 + dd * 64 + lane];       // v0..3
                    ulonglong2 tvB = ts2[jj * 256 + dd * 64 + 32 + lane];  // v4..7
                    #pragma unroll
                    for (int g = 0; g < 4; g++) {
                        float xv = (dd == 0) ? c[g].x : (dd == 1) ? c[g].y
                                 : (dd == 2) ? c[g].z : c[g].w;
                        unsigned long long xx;
                        asm("mov.b64 %0, {%1, %1};" : "=l"(xx) : "f"(xv));
                        asm("fma.rn.f32x2 %0, %1, %2, %0;" : "+l"(acc[g][0]) : "l"(xx), "l"(tvA.x));
                        asm("fma.rn.f32x2 %0, %1, %2, %0;" : "+l"(acc[g][1]) : "l"(xx), "l"(tvA.y));
                        asm("fma.rn.f32x2 %0, %1, %2, %0;" : "+l"(acc[g][2]) : "l"(xx), "l"(tvB.x));
                        asm("fma.rn.f32x2 %0, %1, %2, %0;" : "+l"(acc[g][3]) : "l"(xx), "l"(tvB.y));
                    }
                }
            }

            // unpack 32 partials: vals[g*8 + vp*2 + {0,1}] = (lo,hi) of acc
            float vals[32];
            #pragma unroll
            for (int g = 0; g < 4; g++)
                #pragma unroll
                for (int vp = 0; vp < 4; vp++) {
                    float x, y;
                    asm("mov.b64 {%0, %1}, %2;" : "=f"(x), "=f"(y) : "l"(acc[g][vp]));
                    vals[g * 8 + vp * 2]     = x;
                    vals[g * 8 + vp * 2 + 1] = y;
                }
            butterfly32(vals, lane);

            // transpose via smem slab: row (pass*4+g) gets its 8 v's
            simP[wid * 32 + lane] = vals[0];
            __syncwarp();
            if ((lane >> 2) == pass) {
                int base = wid * 32 + (lane & 3) * 8;
                float4 s0 = *reinterpret_cast<float4*>(&simP[base]);
                float4 s1 = *reinterpret_cast<float4*>(&simP[base + 4]);
                simv[0] = s0.x; simv[1] = s0.y; simv[2] = s0.z; simv[3] = s0.w;
                simv[4] = s1.x; simv[5] = s1.y; simv[6] = s1.z; simv[7] = s1.w;
            }
            __syncwarp();
        }
    }

    // K = exp(-(1 - sim)/0.1); lane owns row rg*32 + lane
    float Kv[8];
    #pragma unroll
    for (int i = 0; i < 8; i++) Kv[i] = active ? expf((simv[i] - 1.0f) * 10.0f) : 0.0f;

    const float uu = 1.0f / (float)M_ROWS;
    float cm[8], cp[8];
    #pragma unroll
    for (int i = 0; i < 8; i++) { cm[i] = 1.0f; cp[i] = 1.0f; }

    // ---- Sinkhorn loop: 1 grid barrier per iteration (R12-verified) ----
    int t = 0;
    for (;;) {
        t++;
        float vals9[9];
        if (active) {
            float err = 0.0f;
            float rr[2];
            #pragma unroll
            for (int b = 0; b < 2; b++) {
                float s = 0.0f, s2 = 0.0f;
                #pragma unroll
                for (int n = 0; n < 4; n++) {
                    s  = fmaf(Kv[b * 4 + n], cm[b * 4 + n], s);
                    s2 = fmaf(Kv[b * 4 + n], cp[b * 4 + n], s2);
                }
                float r    = uu / s;
                float rold = (t == 1) ? 1.0f : uu / s2;   // r0 = ones
                rr[b] = r;
                err += fabsf(r - rold);
            }
            #pragma unroll
            for (int b = 0; b < 2; b++)
                #pragma unroll
                for (int n = 0; n < 4; n++)
                    vals9[b * 4 + n] = Kv[b * 4 + n] * rr[b];
            vals9[8] = err;
        } else {
            #pragma unroll
            for (int i = 0; i < 9; i++) vals9[i] = 0.0f;
        }

        block_reduce<9>(vals9, red);
        const int sl = t & 1;
        if (tid == 0) {
            #pragma unroll
            for (int i = 0; i < 9; i++) g_part[sl][blockIdx.x * 16 + i] = vals9[i];
        }
        grid_barrier(mygen);

        // every block reduces all partials (identical result everywhere)
        float pv[9];
        #pragma unroll
        for (int i = 0; i < 9; i++)
            pv[i] = (tid < NBLK) ? g_part[sl][tid * 16 + i] : 0.0f;
        block_reduce<9>(pv, red);
        if (tid == 0) {
            float e = pv[8] * (1.0f / (2.0f * (float)M_ROWS));
            #pragma unroll
            for (int i = 0; i < 8; i++) bc[i] = 0.25f / pv[i];   // v = 1/N
            bc[8] = (e < SINK_THRESH || t >= SINK_MAX_ITER) ? 1.0f : 0.0f;
        }
        __syncthreads();
        int stop = (bc[8] != 0.0f);
        #pragma unroll
        for (int i = 0; i < 8; i++) { cp[i] = cm[i]; cm[i] = bc[i]; }
        if (stop) break;
    }

    // ---- final: sim_op[b] = sum_m r_T[m] * sum_n c_T[n] K[m,n] sim[m,n] ----
    float ov[2] = {0.0f, 0.0f};
    if (active) {
        #pragma unroll
        for (int b = 0; b < 2; b++) {
            float s = 0.0f, a = 0.0f;
            #pragma unroll
            for (int n = 0; n < 4; n++) {
                s = fmaf(Kv[b * 4 + n], cp[b * 4 + n], s);
                a = fmaf(cm[b * 4 + n] * Kv[b * 4 + n], simv[b * 4 + n], a);
            }
            ov[b] += (uu / s) * a;
        }
    }
    block_reduce<2>(ov, red);
    const int slf = (t + 1) & 1;
    if (tid == 0) {
        g_part[slf][blockIdx.x * 16 + 0] = ov[0];
        g_part[slf][blockIdx.x * 16 + 1] = ov[1];
    }
    grid_barrier(mygen);
    if (blockIdx.x == 0) {
        float pv[2];
        pv[0] = (tid < NBLK) ? g_part[slf][tid * 16 + 0] : 0.0f;
        pv[1] = (tid < NBLK) ? g_part[slf][tid * 16 + 1] : 0.0f;
        block_reduce<2>(pv, red);
        if (tid == 0) {
            float sc = expf(ls[0]);
            out[0] = sc * pv[0];
            out[1] = sc * pv[1];
        }
    }
}

extern "C" void kernel_launch(void* const* d_in, const int* in_sizes, int n_in,
                              void* d_out, int out_size) {
    const float* img = (const float*)d_in[0];
    const float* txt = (const float*)d_in[1];
    const float* ls  = (const float*)d_in[2];
    float* out = (float*)d_out;
    (void)in_sizes; (void)n_in; (void)out_size;

    // idempotent; required for >48KB dynamic smem (R10-proven path)
    (void)cudaFuncSetAttribute((const void*)mg_fused,
                               cudaFuncAttributeMaxDynamicSharedMemorySize,
                               SMEM_TOTAL);
    mg_fused<<<NBLK, NTHR, SMEM_TOTAL>>>(img, txt, ls, out);
}